// round 11
// baseline (speedup 1.0000x reference)
#include <cuda_runtime.h>
#include <cuda_bf16.h>
#include <cstdint>

#define C_CLS   19
#define V_VIEWS 10
#define NQ      38
#define QS      8192
#define M_TOT   (NQ*QS)
#define N_ROWS  190
#define N_PAD   192
#define INV_T   (1.0f/0.07f)
#define L2E     1.44269504f

#define CTA_COLS       2048
#define GRID_X         (M_TOT / CTA_COLS)     // 152
#define TILE_COLS      64
#define TILES_PER_CTA  (CTA_COLS / TILE_COLS) // 32
#define KSTEPS         16

#define SA       132
#define SB       132
#define A_WORDS  (N_PAD * SA)
#define B_WORDS  (TILE_COLS * SB)
#define SMEM_BYTES ((A_WORDS + 2*B_WORDS)*4 + 2*N_PAD*4*2)

__device__ float g_P[N_PAD * QS];
__device__ float g_mxPart[N_PAD * GRID_X];
__device__ float g_sPart [N_PAD * GRID_X];
__device__ float g_mlpp[N_PAD];

__device__ __forceinline__ float fexp2(float x) {
    float y; asm("ex2.approx.ftz.f32 %0, %1;" : "=f"(y) : "f"(x)); return y;
}
__device__ __forceinline__ uint32_t pack_bf16(float x, float y) {
    uint16_t lo = __bfloat16_as_ushort(__float2bfloat16(x));
    uint16_t hi = __bfloat16_as_ushort(__float2bfloat16(y));
    return ((uint32_t)hi << 16) | (uint32_t)lo;
}
__device__ __forceinline__ void mma_bf16(float& d0, float& d1, float& d2, float& d3,
                                         uint32_t a0, uint32_t a1, uint32_t a2, uint32_t a3,
                                         uint32_t b0, uint32_t b1) {
    asm("mma.sync.aligned.m16n8k16.row.col.f32.bf16.bf16.f32 "
        "{%0,%1,%2,%3}, {%4,%5,%6,%7}, {%8,%9}, {%0,%1,%2,%3};\n"
        : "+f"(d0), "+f"(d1), "+f"(d2), "+f"(d3)
        : "r"(a0), "r"(a1), "r"(a2), "r"(a3), "r"(b0), "r"(b1));
}
__device__ __forceinline__ void upd_ms(float& m, float& s, float d) {
    if (d > m) { s = s * fexp2((m - d) * L2E) + 1.0f; m = d; }
    else if (d - m > -30.0f) { s += fexp2((d - m) * L2E); }
}
__device__ __forceinline__ void merge_ms(float& m, float& s, float mo, float so) {
    float nm = fmaxf(m, mo);
    s = s * fexp2((m - nm) * L2E) + so * fexp2((mo - nm) * L2E);
    m = nm;
}

// ============ Kernel 1: fused bf16-MMA GEMM + online neg (max,sumexp) ============
__global__ void __launch_bounds__(256, 1)
gemm_stats_kernel(const float* __restrict__ feat,
                  const int*   __restrict__ label,
                  const float* __restrict__ queue)
{
    extern __shared__ uint32_t sm[];
    uint32_t* AsU   = sm;
    uint32_t* BsU   = sm + A_WORDS;
    float*    sm_mx = (float*)(sm + A_WORDS + 2*B_WORDS);
    float*    sm_s  = sm_mx + 2*N_PAD;
    __shared__ int s_lab[C_CLS];

    const int tid  = threadIdx.x;
    const int lane = tid & 31;
    const int warp = tid >> 5;
    const int wm   = warp & 3;
    const int wn   = warp >> 2;
    const int g    = lane >> 2;
    const int tig  = lane & 3;
    const int b    = blockIdx.x;
    const int q    = b >> 2;                  // queue row/class of this chunk
    const int col0 = b * CTA_COLS;

    if (tid < C_CLS) s_lab[tid] = label[tid];

    // anchor: As[n = v*19+c][k] = feat[c][v][k]/T  (bf16, padded rows)
    {
        const float2* f2 = (const float2*)feat;
        for (int i = tid; i < N_PAD * 128; i += 256) {
            int n = i >> 7, k2 = i & 127;
            uint32_t w = 0u;
            if (n < N_ROWS) {
                int cc = n % C_CLS, vv = n / C_CLS;
                float2 x = f2[(cc * V_VIEWS + vv) * 128 + k2];
                w = pack_bf16(x.x * INV_T, x.y * INV_T);
            }
            AsU[n * SA + k2] = w;
        }
    }

    const float4* q4 = (const float4*)queue;
    float4 st[16];
    // prologue: stage + store tile 0
    #pragma unroll
    for (int i = 0; i < 16; i++) {
        int idx = tid + i * 256;
        st[i] = q4[(size_t)(col0 + (idx >> 6)) * 64 + (idx & 63)];
    }
    {
        uint2* bw = (uint2*)BsU;
        #pragma unroll
        for (int i = 0; i < 16; i++) {
            int idx = tid + i * 256;
            uint2 w; w.x = pack_bf16(st[i].x, st[i].y); w.y = pack_bf16(st[i].z, st[i].w);
            bw[(idx >> 6) * 66 + (idx & 63)] = w;
        }
    }
    __syncthreads();

    float mx6[6], s6[6];
    bool  posS[6];
    int   rowS[6];
    #pragma unroll
    for (int s = 0; s < 6; s++) {
        int mi = s >> 1, h = s & 1;
        int row = wm * 48 + mi * 16 + g + h * 8;
        rowS[s] = row;
        posS[s] = (s_lab[row % C_CLS] == q);
        mx6[s] = -1e30f; s6[s] = 0.0f;
    }

    const uint32_t* pa0 = AsU + (wm * 48 + g) * SA + tig;

    for (int t = 0; t < TILES_PER_CTA; t++) {
        const int  cur     = t & 1;
        const bool hasNext = (t + 1 < TILES_PER_CTA);

        if (hasNext) {
            #pragma unroll
            for (int i = 0; i < 16; i++) {
                int idx = tid + i * 256;
                st[i] = q4[(size_t)(col0 + (t + 1) * 64 + (idx >> 6)) * 64 + (idx & 63)];
            }
        }

        float acc[3][4][4];
        #pragma unroll
        for (int mi = 0; mi < 3; mi++)
            #pragma unroll
            for (int nj = 0; nj < 4; nj++)
                #pragma unroll
                for (int v = 0; v < 4; v++) acc[mi][nj][v] = 0.0f;

        const uint32_t* pb = BsU + cur * B_WORDS + (wn * 32 + g) * SB + tig;

        #pragma unroll
        for (int kk = 0; kk < KSTEPS; kk++) {
            uint32_t a[3][4];
            #pragma unroll
            for (int mi = 0; mi < 3; mi++) {
                const uint32_t* p = pa0 + mi * (16 * SA) + kk * 8;
                a[mi][0] = p[0]; a[mi][1] = p[8 * SA]; a[mi][2] = p[4]; a[mi][3] = p[8 * SA + 4];
            }
            uint32_t bb[4][2];
            #pragma unroll
            for (int nj = 0; nj < 4; nj++) {
                const uint32_t* p = pb + nj * (8 * SB) + kk * 8;
                bb[nj][0] = p[0]; bb[nj][1] = p[4];
            }
            #pragma unroll
            for (int mi = 0; mi < 3; mi++)
                #pragma unroll
                for (int nj = 0; nj < 4; nj++)
                    mma_bf16(acc[mi][nj][0], acc[mi][nj][1], acc[mi][nj][2], acc[mi][nj][3],
                             a[mi][0], a[mi][1], a[mi][2], a[mi][3], bb[nj][0], bb[nj][1]);
        }

        if (hasNext) {
            uint2* bw = (uint2*)(BsU + (cur ^ 1) * B_WORDS);
            #pragma unroll
            for (int i = 0; i < 16; i++) {
                int idx = tid + i * 256;
                uint2 w; w.x = pack_bf16(st[i].x, st[i].y); w.y = pack_bf16(st[i].z, st[i].w);
                bw[(idx >> 6) * 66 + (idx & 63)] = w;
            }
        }

        // epilogue: positives -> g_P; negatives -> running (max, sumexp)
        const int colB = (b & 3) * CTA_COLS + t * 64 + wn * 32 + tig * 2;
        #pragma unroll
        for (int mi = 0; mi < 3; mi++) {
            #pragma unroll
            for (int h = 0; h < 2; h++) {
                const int s = mi * 2 + h;
                if (posS[s]) {
                    const int row = rowS[s];
                    if (row < N_ROWS) {
                        float2* pp = (float2*)(g_P + (size_t)row * QS + colB);
                        #pragma unroll
                        for (int nj = 0; nj < 4; nj++)
                            pp[nj * 4] = make_float2(acc[mi][nj][h * 2], acc[mi][nj][h * 2 + 1]);
                    }
                } else {
                    #pragma unroll
                    for (int nj = 0; nj < 4; nj++) {
                        upd_ms(mx6[s], s6[s], acc[mi][nj][h * 2]);
                        upd_ms(mx6[s], s6[s], acc[mi][nj][h * 2 + 1]);
                    }
                }
            }
        }
        __syncthreads();
    }

    // reduce stats: quad (tig) -> smem per wn -> merge -> global partials
    #pragma unroll
    for (int s = 0; s < 6; s++) {
        #pragma unroll
        for (int off = 1; off <= 2; off <<= 1) {
            float mo = __shfl_xor_sync(0xffffffffu, mx6[s], off);
            float so = __shfl_xor_sync(0xffffffffu, s6[s], off);
            merge_ms(mx6[s], s6[s], mo, so);
        }
    }
    if (tig == 0) {
        #pragma unroll
        for (int s = 0; s < 6; s++) {
            sm_mx[wn * N_PAD + rowS[s]] = mx6[s];
            sm_s [wn * N_PAD + rowS[s]] = s6[s];
        }
    }
    __syncthreads();
    if (tid < N_PAD) {
        float m = sm_mx[tid], ss = sm_s[tid];
        merge_ms(m, ss, sm_mx[N_PAD + tid], sm_s[N_PAD + tid]);
        g_mxPart[tid * GRID_X + b] = m;
        g_sPart [tid * GRID_X + b] = ss;
    }
}

// ============ Kernel 2: per-row merge + positive-term sums ============
__global__ void __launch_bounds__(256)
pass2_kernel(const int* __restrict__ label)
{
    __shared__ float  rm[256], rs[256];
    __shared__ double rd1[256], rd2[256];
    const int n = blockIdx.x;
    const int t = threadIdx.x;
    const int cval = label[n % C_CLS];

    float m = -1e30f, s = 0.0f;
    if (t < GRID_X) { m = g_mxPart[n * GRID_X + t]; s = g_sPart[n * GRID_X + t]; }
    rm[t] = m; rs[t] = s;
    __syncthreads();
    for (int off = 128; off > 0; off >>= 1) {
        if (t < off) {
            float mm = rm[t], sv = rs[t];
            merge_ms(mm, sv, rm[t + off], rs[t + off]);
            rm[t] = mm; rs[t] = sv;
        }
        __syncthreads();
    }
    const float MX = rm[0], S = rs[0];
    const float logS = __logf(S);

    double t1 = 0.0, t2 = 0.0;
    const float* Pr = g_P + (size_t)n * QS;
    for (int j = t; j < QS; j += 256) {
        if (cval == 0 && j == n) continue;       // self-contrast removal
        float x = Pr[j] - MX;
        t1 += (double)x;
        float term;
        if (x > 80.0f)             term = x;
        else if (x < logS - 15.0f) term = logS;
        else                       term = __logf(__expf(x) + S);
        t2 += (double)term;
    }
    rd1[t] = t1; rd2[t] = t2;
    __syncthreads();
    for (int off = 128; off > 0; off >>= 1) {
        if (t < off) { rd1[t] += rd1[t + off]; rd2[t] += rd2[t + off]; }
        __syncthreads();
    }
    if (t == 0) {
        double Pn = (cval == 0) ? (double)(QS - 1) : (double)QS;
        g_mlpp[n] = (float)((rd1[0] - rd2[0]) / Pn);
    }
}

// ============ Kernel 3: final scalar ============
__global__ void pass3_kernel(float* __restrict__ out)
{
    __shared__ double r[64];
    int t = threadIdx.x;
    double v = 0.0;
    for (int i = t; i < N_ROWS; i += 64) v += (double)g_mlpp[i];
    r[t] = v; __syncthreads();
    for (int off = 32; off > 0; off >>= 1) {
        if (t < off) r[t] += r[t + off];
        __syncthreads();
    }
    if (t == 0) out[0] = (float)(-(r[0] / (double)N_ROWS) * 0.5);
}

extern "C" void kernel_launch(void* const* d_in, const int* in_sizes, int n_in,
                              void* d_out, int out_size)
{
    const float* feat  = (const float*)d_in[0];
    const int*   label = (const int*)d_in[1];
    const float* queue = (const float*)d_in[2];
    float* out = (float*)d_out;

    cudaFuncSetAttribute(gemm_stats_kernel,
                         cudaFuncAttributeMaxDynamicSharedMemorySize, SMEM_BYTES);
    gemm_stats_kernel<<<GRID_X, 256, SMEM_BYTES>>>(feat, label, queue);
    pass2_kernel<<<N_ROWS, 256>>>(label);
    pass3_kernel<<<1, 64>>>(out);
}